// round 10
// baseline (speedup 1.0000x reference)
#include <cuda_runtime.h>

#define NB 32
#define LL 1024
#define TT 64
#define KSEG 9
#define NCH (2 * KSEG - 2)   // 16 chains per batch

#define FMA2(d,a,b,c) asm("fma.rn.f32x2 %0, %1, %2, %3;" : "=l"(d) : "l"(a), "l"(b), "l"(c))
#define MUL2(d,a,b)   asm("mul.rn.f32x2 %0, %1, %2;"     : "=l"(d) : "l"(a), "l"(b))
#define ADD2(d,a,b)   asm("add.rn.f32x2 %0, %1, %2;"     : "=l"(d) : "l"(a), "l"(b))
#define UNPACK2(lo,hi,v) asm("mov.b64 {%0,%1}, %2;" : "=f"(lo), "=f"(hi) : "l"(v))
#define PACK2(v,lo,hi)   asm("mov.b64 %0, {%1,%2};" : "=l"(v) : "f"(lo), "f"(hi))

// segment cut points: c[k] = (k*1023)/9
__device__ __constant__ int d_cut[KSEG + 1] =
    {0, 113, 227, 341, 454, 568, 682, 795, 909, 1023};

// device-global scratch (sanctioned no-alloc scratch)
__device__ float g_vec[NB][NCH][TT];   // normalized chain output vectors
__device__ int   g_ex[NB][NCH];        // integer pow2 exponent offsets
__device__ float g_gen[NB];            // generic-path result
__device__ int   g_isgen[NB];

__global__ __launch_bounds__(64)
void crf_seg_kernel(const float* __restrict__ logits,     // [B,L,T]
                    const float* __restrict__ trans,      // [T,T]
                    const float* __restrict__ start_s,    // [T]
                    const float* __restrict__ end_s,      // [T]
                    const int* __restrict__ mask)         // [B,L] bool as int32
{
    const int b   = blockIdx.x >> 4;
    const int cid = blockIdx.x & 15;     // chain id 0..15, one per 64-thr CTA
    const int tid = threadIdx.x;         // = output state j, 0..63

    // double-buffered 64-float vector; broadcast reads, stride-1 writes
    __shared__ __align__(16) float xs[2][TT];
    __shared__ int s_red[2];
    __shared__ int s_end;

    // ---- end_idx = count(mask != 0) - 1 ; mask stored as int32 ----
    {
        const int4* mb = reinterpret_cast<const int4*>(mask + (size_t)b * LL);
        int cnt = 0;
        #pragma unroll
        for (int q = 0; q < 4; ++q) {
            int4 m = mb[tid * 4 + q];    // 64 thr * 16 ints = 1024
            cnt += (m.x != 0) + (m.y != 0) + (m.z != 0) + (m.w != 0);
        }
        #pragma unroll
        for (int o = 16; o > 0; o >>= 1) cnt += __shfl_xor_sync(~0u, cnt, o);
        if ((tid & 31) == 0) s_red[tid >> 5] = cnt;
        __syncthreads();
        if (tid == 0) s_end = s_red[0] + s_red[1] - 1;
        __syncthreads();
    }
    const int endi = s_end;
    const bool generic = (endi != 1023);
    if (generic && cid != 0) return;

    const bool bwd = (!generic) && (cid >= KSEG - 1);   // cid >= 8
    const float esc = generic ? 1.0f : 0.0078125f;      // fold 2^-7 into E'

    // ---- E' slice for output state tid: 32 packed input-pairs (64 regs) ----
    // fwd: column tid of E (E[i][tid]); bwd: row tid of E (E[tid][i])
    unsigned long long e2[32];
    #pragma unroll
    for (int p = 0; p < 32; ++p) {
        int i0 = bwd ? (tid * TT + 2 * p)     : ((2 * p)     * TT + tid);
        int i1 = bwd ? (tid * TT + 2 * p + 1) : ((2 * p + 1) * TT + tid);
        float lo = __expf(__ldg(&trans[i0])) * esc;
        float hi = __expf(__ldg(&trans[i1])) * esc;
        PACK2(e2[p], lo, hi);
    }

    // lg[t*TT] = logits[b][t][tid]
    const float* lg = logits + (size_t)b * LL * TT + tid;

    int buf = 0;

    // full 64-input dot for this thread's single output state
    auto dot = [&]() -> float {
        const ulonglong2* bp = reinterpret_cast<const ulonglong2*>(xs[buf]);
        unsigned long long A0, A1, A2, A3;
        {
            ulonglong2 v = bp[0], w = bp[1];
            MUL2(A0, v.x, e2[0]); MUL2(A1, v.y, e2[1]);
            MUL2(A2, w.x, e2[2]); MUL2(A3, w.y, e2[3]);
        }
        {
            ulonglong2 v = bp[2], w = bp[3];
            FMA2(A0, v.x, e2[4], A0); FMA2(A1, v.y, e2[5], A1);
            FMA2(A2, w.x, e2[6], A2); FMA2(A3, w.y, e2[7], A3);
        }
        {
            ulonglong2 v = bp[4], w = bp[5];
            FMA2(A0, v.x, e2[8],  A0); FMA2(A1, v.y, e2[9],  A1);
            FMA2(A2, w.x, e2[10], A2); FMA2(A3, w.y, e2[11], A3);
        }
        {
            ulonglong2 v = bp[6], w = bp[7];
            FMA2(A0, v.x, e2[12], A0); FMA2(A1, v.y, e2[13], A1);
            FMA2(A2, w.x, e2[14], A2); FMA2(A3, w.y, e2[15], A3);
        }
        {
            ulonglong2 v = bp[8], w = bp[9];
            FMA2(A0, v.x, e2[16], A0); FMA2(A1, v.y, e2[17], A1);
            FMA2(A2, w.x, e2[18], A2); FMA2(A3, w.y, e2[19], A3);
        }
        {
            ulonglong2 v = bp[10], w = bp[11];
            FMA2(A0, v.x, e2[20], A0); FMA2(A1, v.y, e2[21], A1);
            FMA2(A2, w.x, e2[22], A2); FMA2(A3, w.y, e2[23], A3);
        }
        {
            ulonglong2 v = bp[12], w = bp[13];
            FMA2(A0, v.x, e2[24], A0); FMA2(A1, v.y, e2[25], A1);
            FMA2(A2, w.x, e2[26], A2); FMA2(A3, w.y, e2[27], A3);
        }
        {
            ulonglong2 v = bp[14], w = bp[15];
            FMA2(A0, v.x, e2[28], A0); FMA2(A1, v.y, e2[29], A1);
            FMA2(A2, w.x, e2[30], A2); FMA2(A3, w.y, e2[31], A3);
        }
        ADD2(A0, A0, A1); ADD2(A2, A2, A3); ADD2(A0, A0, A2);
        float lo, hi;
        UNPACK2(lo, hi, A0);
        return lo + hi;
    };

    auto step_fast = [&](float graw) {
        float d = dot();
        xs[buf ^ 1][tid] = d * __expf(graw);
        buf ^= 1;
        __syncthreads();
    };

    auto writeout = [&](float x, int S) {
        float bb = xs[buf][0];               // broadcast read, all threads
        int   ex = ((__float_as_int(bb) >> 23) & 255) - 127;
        float scale = __int_as_float((127 - ex) << 23);
        g_vec[b][cid][tid] = x * scale;
        if (tid == 0) g_ex[b][cid] = ex + 7 * S;
    };

    if (generic) {
        // ==== correct fallback: full forward with per-step pow2 renorm ====
        float v0 = __expf(lg[0] + __ldg(&start_s[tid]) +
                          ((endi == 0) ? __ldg(&end_s[tid]) : 0.f));
        xs[0][tid] = v0;
        __syncthreads();
        int exoff = 0;
        #pragma unroll 1
        for (int t = 1; t <= endi; ++t) {
            float bb = xs[buf][0];
            int   ex = ((__float_as_int(bb) >> 23) & 255) - 127;
            float scale = __int_as_float((127 - ex) << 23);
            float g = lg[(size_t)t * TT] +
                      ((t == endi) ? __ldg(&end_s[tid]) : 0.f);
            float d = dot();
            xs[buf ^ 1][tid] = d * (scale * __expf(g));
            exoff += ex;
            buf ^= 1;
            __syncthreads();
        }
        // reduce 64 values: warp-local + cross-warp via smem
        float s = xs[buf][tid];
        #pragma unroll
        for (int o = 16; o > 0; o >>= 1) s += __shfl_xor_sync(~0u, s, o);
        if ((tid & 31) == 0)
            reinterpret_cast<float*>(s_red)[tid >> 5] = s;
        __syncthreads();
        if (tid == 0) {
            float tot = reinterpret_cast<float*>(s_red)[0] +
                        reinterpret_cast<float*>(s_red)[1];
            g_gen[b] = __int2float_rn(exoff) * 0.693147180559945f + __logf(tot);
            g_isgen[b] = 1;
        }
        return;
    }
    if (cid == 0 && tid == 0) g_isgen[b] = 0;

    if (!bwd) {
        // ========== forward chains: R (cid 0), Q_k (cid k-1, k=2..8) ==========
        int lo, hi;
        if (cid == 0) {
            lo = 1; hi = d_cut[1];
            xs[0][tid] = __expf(lg[0] + __ldg(&start_s[tid]));
        } else {
            int k = cid + 1;
            lo = d_cut[k - 1] + 1; hi = d_cut[k];
            xs[0][tid] = 1.0f;
        }
        __syncthreads();

        float gA = lg[(size_t)lo * TT];
        float gB = lg[(size_t)(lo + 1) * TT];
        int t = lo;
        #pragma unroll 1
        for (; t + 1 <= hi; t += 2) {
            step_fast(gA); gA = lg[(size_t)(t + 2) * TT];
            step_fast(gB); gB = lg[(size_t)(t + 3) * TT];
        }
        if (t <= hi) step_fast(gA);

        writeout(xs[buf][tid], hi - lo + 1);
    } else {
        // ===== backward chains: P_k (cid k+6, k=2..8), W (cid 15) =====
        int lo0, hi0, S;
        if (cid == NCH - 1) {            // W
            lo0 = d_cut[KSEG - 1] + 1;   // 910
            hi0 = 1022;
            xs[0][tid] = __expf(lg[(size_t)1023 * TT] + __ldg(&end_s[tid]));
            S = 1023 - d_cut[KSEG - 1];
        } else {                         // P_k
            int k = cid - 6;
            lo0 = d_cut[k - 1] + 1;
            hi0 = d_cut[k] - 1;
            xs[0][tid] = __expf(lg[(size_t)d_cut[k] * TT]);
            S = d_cut[k] - d_cut[k - 1];
        }
        __syncthreads();

        float gA = lg[(size_t)hi0 * TT];
        float gB = lg[(size_t)(hi0 - 1) * TT];
        int t = hi0;
        #pragma unroll 1
        for (; t - 1 >= lo0; t -= 2) {
            step_fast(gA); gA = lg[(size_t)(t - 2) * TT];
            step_fast(gB); gB = lg[(size_t)(t - 3) * TT];
        }
        if (t >= lo0) step_fast(gA);

        float d = dot();                 // epilogue matvec p = E' u, no eg
        writeout(d, S);
    }
}

// telescoped rank-1 combine (q-chain scales cancel exactly):
// logZ = sum_{k=2}^{K-1}[log(p_k·x_{k-1}) − log Σq_k] + log(w·q_{K-1})
//        + ln2·(exR + exW + Σ exP_k)
__global__ void crf_combine_kernel(float* __restrict__ out)
{
    const int b = blockIdx.x;    // batch
    const int l = threadIdx.x;   // lane
    if (g_isgen[b]) { if (l == 0) out[b] = g_gen[b]; return; }

    float va[NCH], vb[NCH];
    #pragma unroll
    for (int c = 0; c < NCH; ++c) {
        va[c] = g_vec[b][c][l];
        vb[c] = g_vec[b][c][l + 32];
    }

    float acc = 0.0f;
    #pragma unroll
    for (int k = 2; k <= KSEG - 1; ++k) {
        float d = va[k + 6] * va[k - 2] + vb[k + 6] * vb[k - 2];
        float s = va[k - 1] + vb[k - 1];
        #pragma unroll
        for (int o = 16; o > 0; o >>= 1) {
            d += __shfl_xor_sync(~0u, d, o);
            s += __shfl_xor_sync(~0u, s, o);
        }
        acc += __logf(d) - __logf(s);
    }
    {
        float d = va[NCH - 1] * va[KSEG - 2] + vb[NCH - 1] * vb[KSEG - 2];
        #pragma unroll
        for (int o = 16; o > 0; o >>= 1) d += __shfl_xor_sync(~0u, d, o);
        acc += __logf(d);
    }

    if (l == 0) {
        int ex = g_ex[b][0] + g_ex[b][NCH - 1];
        #pragma unroll
        for (int c = NCH / 2; c <= NCH - 2; ++c) ex += g_ex[b][c];
        out[b] = acc + __int2float_rn(ex) * 0.693147180559945f;
    }
}

extern "C" void kernel_launch(void* const* d_in, const int* in_sizes, int n_in,
                              void* d_out, int out_size) {
    const float* logits        = (const float*)d_in[0];
    const float* transitions   = (const float*)d_in[1];
    const float* start_states  = (const float*)d_in[2];
    const float* end_states    = (const float*)d_in[3];
    const int*   mask          = (const int*)d_in[4];
    float* out = (float*)d_out;
    (void)in_sizes; (void)n_in; (void)out_size;

    crf_seg_kernel<<<NB * NCH, 64>>>(logits, transitions, start_states,
                                     end_states, mask);
    crf_combine_kernel<<<NB, 32>>>(out);
}

// round 11
// speedup vs baseline: 1.1868x; 1.1868x over previous
#include <cuda_runtime.h>

#define NB 32
#define LL 1024
#define TT 64
#define KSEG 9
#define NCH (2 * KSEG - 2)   // 16 chains per batch

#define FMA2(d,a,b,c) asm("fma.rn.f32x2 %0, %1, %2, %3;" : "=l"(d) : "l"(a), "l"(b), "l"(c))
#define MUL2(d,a,b)   asm("mul.rn.f32x2 %0, %1, %2;"     : "=l"(d) : "l"(a), "l"(b))
#define ADD2(d,a,b)   asm("add.rn.f32x2 %0, %1, %2;"     : "=l"(d) : "l"(a), "l"(b))
#define UNPACK2(lo,hi,v) asm("mov.b64 {%0,%1}, %2;" : "=f"(lo), "=f"(hi) : "l"(v))
#define PACK2(v,lo,hi)   asm("mov.b64 %0, {%1,%2};" : "=l"(v) : "f"(lo), "f"(hi))

// segment cut points: c[k] = (k*1023)/9
__device__ __constant__ int d_cut[KSEG + 1] =
    {0, 113, 227, 341, 454, 568, 682, 795, 909, 1023};

// device-global scratch (sanctioned no-alloc scratch)
__device__ float g_vec[NB][NCH][TT];   // normalized chain output vectors
__device__ int   g_ex[NB][NCH];        // integer pow2 exponent offsets
__device__ int   g_cnt[NB];            // arrival counters (self-resetting)

__global__ __launch_bounds__(64)
void crf_seg_kernel(const float* __restrict__ logits,     // [B,L,T]
                    const float* __restrict__ trans,      // [T,T]
                    const float* __restrict__ start_s,    // [T]
                    const float* __restrict__ end_s,      // [T]
                    const int* __restrict__ mask,         // [B,L] bool as int32
                    float* __restrict__ out)              // [B]
{
    const int b   = blockIdx.x >> 4;
    const int cid = blockIdx.x & 15;     // chain id 0..15, one per 64-thr CTA
    const int tid = threadIdx.x;         // = output state j, 0..63

    __shared__ __align__(16) float xs[2][TT];
    __shared__ int s_red[2];
    __shared__ int s_end;
    __shared__ int s_win;

    // ---- end_idx = count(mask != 0) - 1 ; mask stored as int32 ----
    {
        const int4* mb = reinterpret_cast<const int4*>(mask + (size_t)b * LL);
        int cnt = 0;
        #pragma unroll
        for (int q = 0; q < 4; ++q) {
            int4 m = mb[tid * 4 + q];    // 64 thr * 16 ints = 1024
            cnt += (m.x != 0) + (m.y != 0) + (m.z != 0) + (m.w != 0);
        }
        #pragma unroll
        for (int o = 16; o > 0; o >>= 1) cnt += __shfl_xor_sync(~0u, cnt, o);
        if ((tid & 31) == 0) s_red[tid >> 5] = cnt;
        __syncthreads();
        if (tid == 0) s_end = s_red[0] + s_red[1] - 1;
        __syncthreads();
    }
    const int endi = s_end;
    const bool generic = (endi != 1023);
    if (generic && cid != 0) return;

    const bool bwd = (!generic) && (cid >= KSEG - 1);   // cid >= 8
    const float esc = generic ? 1.0f : 0.0078125f;      // fold 2^-7 into E'

    // ---- E' slice for output state tid: 32 packed input-pairs ----
    unsigned long long e2[32];
    #pragma unroll
    for (int p = 0; p < 32; ++p) {
        int i0 = bwd ? (tid * TT + 2 * p)     : ((2 * p)     * TT + tid);
        int i1 = bwd ? (tid * TT + 2 * p + 1) : ((2 * p + 1) * TT + tid);
        float lo = __expf(__ldg(&trans[i0])) * esc;
        float hi = __expf(__ldg(&trans[i1])) * esc;
        PACK2(e2[p], lo, hi);
    }

    const float* lg = logits + (size_t)b * LL * TT + tid;
    int buf = 0;

    auto dot = [&]() -> float {
        const ulonglong2* bp = reinterpret_cast<const ulonglong2*>(xs[buf]);
        unsigned long long A0, A1, A2, A3;
        {
            ulonglong2 v = bp[0], w = bp[1];
            MUL2(A0, v.x, e2[0]); MUL2(A1, v.y, e2[1]);
            MUL2(A2, w.x, e2[2]); MUL2(A3, w.y, e2[3]);
        }
        {
            ulonglong2 v = bp[2], w = bp[3];
            FMA2(A0, v.x, e2[4], A0); FMA2(A1, v.y, e2[5], A1);
            FMA2(A2, w.x, e2[6], A2); FMA2(A3, w.y, e2[7], A3);
        }
        {
            ulonglong2 v = bp[4], w = bp[5];
            FMA2(A0, v.x, e2[8],  A0); FMA2(A1, v.y, e2[9],  A1);
            FMA2(A2, w.x, e2[10], A2); FMA2(A3, w.y, e2[11], A3);
        }
        {
            ulonglong2 v = bp[6], w = bp[7];
            FMA2(A0, v.x, e2[12], A0); FMA2(A1, v.y, e2[13], A1);
            FMA2(A2, w.x, e2[14], A2); FMA2(A3, w.y, e2[15], A3);
        }
        {
            ulonglong2 v = bp[8], w = bp[9];
            FMA2(A0, v.x, e2[16], A0); FMA2(A1, v.y, e2[17], A1);
            FMA2(A2, w.x, e2[18], A2); FMA2(A3, w.y, e2[19], A3);
        }
        {
            ulonglong2 v = bp[10], w = bp[11];
            FMA2(A0, v.x, e2[20], A0); FMA2(A1, v.y, e2[21], A1);
            FMA2(A2, w.x, e2[22], A2); FMA2(A3, w.y, e2[23], A3);
        }
        {
            ulonglong2 v = bp[12], w = bp[13];
            FMA2(A0, v.x, e2[24], A0); FMA2(A1, v.y, e2[25], A1);
            FMA2(A2, w.x, e2[26], A2); FMA2(A3, w.y, e2[27], A3);
        }
        {
            ulonglong2 v = bp[14], w = bp[15];
            FMA2(A0, v.x, e2[28], A0); FMA2(A1, v.y, e2[29], A1);
            FMA2(A2, w.x, e2[30], A2); FMA2(A3, w.y, e2[31], A3);
        }
        ADD2(A0, A0, A1); ADD2(A2, A2, A3); ADD2(A0, A0, A2);
        float lo, hi;
        UNPACK2(lo, hi, A0);
        return lo + hi;
    };

    auto step_fast = [&](float graw) {
        float d = dot();
        xs[buf ^ 1][tid] = d * __expf(graw);
        buf ^= 1;
        __syncthreads();
    };

    auto writeout = [&](float x, int S) {
        float bb = xs[buf][0];
        int   ex = ((__float_as_int(bb) >> 23) & 255) - 127;
        float scale = __int_as_float((127 - ex) << 23);
        g_vec[b][cid][tid] = x * scale;
        if (tid == 0) g_ex[b][cid] = ex + 7 * S;
    };

    if (generic) {
        // ==== correct fallback: full forward with per-step pow2 renorm ====
        xs[0][tid] = __expf(lg[0] + __ldg(&start_s[tid]) +
                            ((endi == 0) ? __ldg(&end_s[tid]) : 0.f));
        __syncthreads();
        int exoff = 0;
        #pragma unroll 1
        for (int t = 1; t <= endi; ++t) {
            float bb = xs[buf][0];
            int   ex = ((__float_as_int(bb) >> 23) & 255) - 127;
            float scale = __int_as_float((127 - ex) << 23);
            float g = lg[(size_t)t * TT] +
                      ((t == endi) ? __ldg(&end_s[tid]) : 0.f);
            float d = dot();
            xs[buf ^ 1][tid] = d * (scale * __expf(g));
            exoff += ex;
            buf ^= 1;
            __syncthreads();
        }
        float s = xs[buf][tid];
        #pragma unroll
        for (int o = 16; o > 0; o >>= 1) s += __shfl_xor_sync(~0u, s, o);
        if ((tid & 31) == 0)
            reinterpret_cast<float*>(s_red)[tid >> 5] = s;
        __syncthreads();
        if (tid == 0) {
            float tot = reinterpret_cast<float*>(s_red)[0] +
                        reinterpret_cast<float*>(s_red)[1];
            out[b] = __int2float_rn(exoff) * 0.693147180559945f + __logf(tot);
        }
        return;
    }

    if (!bwd) {
        // ========== forward chains: R (cid 0), Q_k (cid k-1, k=2..8) ==========
        int lo, hi;
        if (cid == 0) {
            lo = 1; hi = d_cut[1];
            xs[0][tid] = __expf(lg[0] + __ldg(&start_s[tid]));
        } else {
            int k = cid + 1;
            lo = d_cut[k - 1] + 1; hi = d_cut[k];
            xs[0][tid] = 1.0f;
        }
        __syncthreads();

        // distance-6 prefetch: coverage ~6 steps > L2 latency
        float g0 = lg[(size_t)(lo    ) * TT];
        float g1 = lg[(size_t)(lo + 1) * TT];
        float g2 = lg[(size_t)(lo + 2) * TT];
        float g3 = lg[(size_t)(lo + 3) * TT];
        float g4 = lg[(size_t)(lo + 4) * TT];
        float g5 = lg[(size_t)(lo + 5) * TT];
        int t = lo;
        #pragma unroll 1
        for (; t + 5 <= hi; t += 6) {
            step_fast(g0); g0 = lg[(size_t)(t + 6)  * TT];
            step_fast(g1); g1 = lg[(size_t)(t + 7)  * TT];
            step_fast(g2); g2 = lg[(size_t)(t + 8)  * TT];
            step_fast(g3); g3 = lg[(size_t)(t + 9)  * TT];
            step_fast(g4); g4 = lg[(size_t)(t + 10) * TT];
            step_fast(g5); g5 = lg[(size_t)(t + 11) * TT];
        }
        if (t <= hi) { step_fast(g0); ++t; }
        if (t <= hi) { step_fast(g1); ++t; }
        if (t <= hi) { step_fast(g2); ++t; }
        if (t <= hi) { step_fast(g3); ++t; }
        if (t <= hi) { step_fast(g4); ++t; }

        writeout(xs[buf][tid], hi - lo + 1);
    } else {
        // ===== backward chains: P_k (cid k+6, k=2..8), W (cid 15) =====
        int lo0, hi0, S;
        if (cid == NCH - 1) {            // W
            lo0 = d_cut[KSEG - 1] + 1;   // 910
            hi0 = 1022;
            xs[0][tid] = __expf(lg[(size_t)1023 * TT] + __ldg(&end_s[tid]));
            S = 1023 - d_cut[KSEG - 1];
        } else {                         // P_k
            int k = cid - 6;
            lo0 = d_cut[k - 1] + 1;
            hi0 = d_cut[k] - 1;
            xs[0][tid] = __expf(lg[(size_t)d_cut[k] * TT]);
            S = d_cut[k] - d_cut[k - 1];
        }
        __syncthreads();

        float g0 = lg[(size_t)(hi0    ) * TT];
        float g1 = lg[(size_t)(hi0 - 1) * TT];
        float g2 = lg[(size_t)(hi0 - 2) * TT];
        float g3 = lg[(size_t)(hi0 - 3) * TT];
        float g4 = lg[(size_t)(hi0 - 4) * TT];
        float g5 = lg[(size_t)(hi0 - 5) * TT];
        int t = hi0;
        #pragma unroll 1
        for (; t - 5 >= lo0; t -= 6) {
            step_fast(g0); g0 = lg[(size_t)(t - 6)  * TT];
            step_fast(g1); g1 = lg[(size_t)(t - 7)  * TT];
            step_fast(g2); g2 = lg[(size_t)(t - 8)  * TT];
            step_fast(g3); g3 = lg[(size_t)(t - 9)  * TT];
            step_fast(g4); g4 = lg[(size_t)(t - 10) * TT];
            step_fast(g5); g5 = lg[(size_t)(t - 11) * TT];
        }
        if (t >= lo0) { step_fast(g0); --t; }
        if (t >= lo0) { step_fast(g1); --t; }
        if (t >= lo0) { step_fast(g2); --t; }
        if (t >= lo0) { step_fast(g3); --t; }
        if (t >= lo0) { step_fast(g4); --t; }

        float d = dot();                 // epilogue matvec p = E' u, no eg
        writeout(d, S);
    }

    // ---- fused combine: last CTA of this batch reduces all 16 chains ----
    __threadfence();
    __syncthreads();
    if (tid == 0) {
        int old = atomicAdd(&g_cnt[b], 1);
        s_win = (old == NCH - 1);
    }
    __syncthreads();
    if (!s_win) return;
    __threadfence();

    if (tid < 32) {
        const int l = tid;
        float va[NCH], vb[NCH];
        #pragma unroll
        for (int c = 0; c < NCH; ++c) {
            va[c] = g_vec[b][c][l];
            vb[c] = g_vec[b][c][l + 32];
        }

        float acc = 0.0f;
        #pragma unroll
        for (int k = 2; k <= KSEG - 1; ++k) {
            float d = va[k + 6] * va[k - 2] + vb[k + 6] * vb[k - 2];
            float s = va[k - 1] + vb[k - 1];
            #pragma unroll
            for (int o = 16; o > 0; o >>= 1) {
                d += __shfl_xor_sync(~0u, d, o);
                s += __shfl_xor_sync(~0u, s, o);
            }
            acc += __logf(d) - __logf(s);
        }
        {
            float d = va[NCH - 1] * va[KSEG - 2] + vb[NCH - 1] * vb[KSEG - 2];
            #pragma unroll
            for (int o = 16; o > 0; o >>= 1) d += __shfl_xor_sync(~0u, d, o);
            acc += __logf(d);
        }

        if (l == 0) {
            int ex = g_ex[b][0] + g_ex[b][NCH - 1];
            #pragma unroll
            for (int c = NCH / 2; c <= NCH - 2; ++c) ex += g_ex[b][c];
            out[b] = acc + __int2float_rn(ex) * 0.693147180559945f;
            g_cnt[b] = 0;                // reset for next graph replay
        }
    }
}

extern "C" void kernel_launch(void* const* d_in, const int* in_sizes, int n_in,
                              void* d_out, int out_size) {
    const float* logits        = (const float*)d_in[0];
    const float* transitions   = (const float*)d_in[1];
    const float* start_states  = (const float*)d_in[2];
    const float* end_states    = (const float*)d_in[3];
    const int*   mask          = (const int*)d_in[4];
    float* out = (float*)d_out;
    (void)in_sizes; (void)n_in; (void)out_size;

    crf_seg_kernel<<<NB * NCH, 64>>>(logits, transitions, start_states,
                                     end_states, mask, out);
}